// round 4
// baseline (speedup 1.0000x reference)
#include <cuda_runtime.h>

// LossFunction: fused IoU + smooth-L1 multi-loss over (B=256, N=8192, F=13).
//
// R4: algebraic weight split.
//   total_elemwise = c_base * sum(huber over ALL 13 features)       <- phase 1
//                  + (c2-c_base) * sum(huber over f=0..3)           <- phase 2
//                  + (c3-c_base) * huber at f=12                    <- phase 2
// Phase 1: pure streaming float4 accumulate, no indexing, no smem.
// Phase 2: per-row gather of features {0..3,12} (needed for IoU anyway),
//          served from L2 (tile just streamed by this block).

#define F 13
#define THREADS 256
#define ROWS_TILE 1024
// float4s per tile per tensor = ROWS_TILE*F/4 = 3328 = 13 * THREADS (exact)

__device__ __forceinline__ float huber(float a, float b) {
    float d = fabsf(a - b);
    return d < 1.0f ? 0.5f * d * d : d - 0.5f;
}

__global__ void init_out_kernel(float* out) {
    out[0] = 0.0f;
}

__global__ __launch_bounds__(THREADS, 4)
void loss_kernel(const float* __restrict__ tg,
                 const float* __restrict__ pr,
                 float* __restrict__ out,
                 long long rows,
                 float c1, float cbase, float c2corr, float c3corr) {
    long long row0 = (long long)blockIdx.x * ROWS_TILE;
    long long rem  = rows - row0;
    int nrows = rem < ROWS_TILE ? (int)rem : ROWS_TILE;

    const float* tbase = tg + row0 * F;
    const float* pbase = pr + row0 * F;

    // ---- Phase 1: uniform-weight streaming over all 13*nrows floats ----
    float a0 = 0.0f, a1 = 0.0f, a2 = 0.0f, a3 = 0.0f;  // 4 accumulators

    if (nrows == ROWS_TILE) {
        const float4* t4 = (const float4*)tbase;
        const float4* p4 = (const float4*)pbase;
        int idx = threadIdx.x;
        #pragma unroll
        for (int k = 0; k < 13; k++) {
            float4 t = t4[idx];
            float4 p = p4[idx];
            a0 += huber(t.x, p.x);
            a1 += huber(t.y, p.y);
            a2 += huber(t.z, p.z);
            a3 += huber(t.w, p.w);
            idx += THREADS;
        }
    } else {
        int nflt = nrows * F;
        for (int i = threadIdx.x; i < nflt; i += THREADS)
            a0 += huber(tbase[i], pbase[i]);
    }
    float acc = (a0 + a1 + a2 + a3) * cbase;

    // ---- Phase 2: per-row corrections + IoU from L2-hot gathers ----
    for (int r = threadIdx.x; r < nrows; r += THREADS) {
        const float* tr = tbase + r * F;
        const float* pq = pbase + r * F;
        float t0 = tr[0], t1 = tr[1], t2 = tr[2], t3 = tr[3], t12 = tr[12];
        float p0 = pq[0], p1 = pq[1], p2 = pq[2], p3 = pq[3], p12 = pq[12];

        // loss2 correction (weight c2 - cbase over box features)
        float s2 = huber(t0, p0) + huber(t1, p1) + huber(t2, p2) + huber(t3, p3);
        acc += c2corr * s2;

        // loss3 correction (weight c3 - cbase on last feature)
        acc += c3corr * huber(t12, p12);

        // loss1: IoU vs 1
        float xx1 = fmaxf(t0, p0);
        float yy1 = fmaxf(t1, p1);
        float xx2 = fminf(t2, p2);
        float yy2 = fminf(t3, p3);
        float w = fmaxf(xx2 - xx1, 0.0f);
        float h = fmaxf(yy2 - yy1, 0.0f);
        float inter = w * h;
        float area1 = (t2 - t0) * (t3 - t1);
        float area2 = (p2 - p0) * (p3 - p1);
        float iou = inter / (area1 + area2 - inter + 1e-7f);
        acc += c1 * huber(1.0f, iou);
    }

    // ---- Block reduction + single atomic ----
    #pragma unroll
    for (int off = 16; off > 0; off >>= 1)
        acc += __shfl_xor_sync(0xFFFFFFFFu, acc, off);

    __shared__ float warp_part[THREADS / 32];
    int lane = threadIdx.x & 31;
    int wid  = threadIdx.x >> 5;
    if (lane == 0) warp_part[wid] = acc;
    __syncthreads();

    if (wid == 0) {
        float v = lane < (THREADS / 32) ? warp_part[lane] : 0.0f;
        #pragma unroll
        for (int off = 4; off > 0; off >>= 1)
            v += __shfl_xor_sync(0xFFFFFFFFu, v, off);
        if (lane == 0) atomicAdd(out, v);
    }
}

extern "C" void kernel_launch(void* const* d_in, const int* in_sizes, int n_in,
                              void* d_out, int out_size) {
    const float* targets = (const float*)d_in[0];
    const float* preds   = (const float*)d_in[1];
    float* out = (float*)d_out;

    long long total = (long long)in_sizes[0];
    long long rows  = total / F;  // B*N = 2,097,152

    float inv = 1.0f / (float)rows;
    // True per-element weights:
    //   f in [0,4):  inv/4          (loss2, mean over rows*4)
    //   f in [4,12): 0.5 * inv/8    (loss4*0.5, mean over rows*8) = inv/16
    //   f == 12:     inv            (loss3, mean over rows)
    float cbase  = inv * 0.0625f;           // inv/16, applied uniformly
    float c2corr = inv * 0.25f - cbase;     // 3*inv/16
    float c3corr = inv - cbase;             // 15*inv/16
    float c1     = inv;                     // loss1 mean

    int grid = (int)((rows + ROWS_TILE - 1) / ROWS_TILE);

    init_out_kernel<<<1, 1>>>(out);
    loss_kernel<<<grid, THREADS>>>(targets, preds, out, rows,
                                   c1, cbase, c2corr, c3corr);
}